// round 2
// baseline (speedup 1.0000x reference)
#include <cuda_runtime.h>
#include <cuda_bf16.h>
#include <math.h>

#define NN 30000
#define EE 480000
#define D_IN 128
#define D_HID 256
#define EPS 1e-5f

// ---------------- scratch (device globals; no allocation) ----------------
__device__ float g_m1 [NN * D_IN];    // encoder pool messages
__device__ float g_agg1[NN * D_IN];   // encoder segment-max
__device__ float g_h1 [NN * D_HID];   // encoder output
__device__ float g_cls[NN * 5];       // softmax(node_pred)
__device__ float g_P  [NN * D_HID];   // h1 @ W1[0:256]
__device__ float g_Q  [NN * D_HID];   // h1 @ W1[267:523]
__device__ float g_m2 [NN * D_HID];   // decoder pool messages
__device__ float g_agg2[NN * D_HID];  // decoder segment-max

// ---------------- zero the aggregation buffers ----------------
__global__ void zero_aggs() {
    int n1 = NN * D_IN, n2 = NN * D_HID;
    for (int i = blockIdx.x * blockDim.x + threadIdx.x; i < n2; i += gridDim.x * blockDim.x) {
        if (i < n1) g_agg1[i] = 0.f;
        g_agg2[i] = 0.f;
    }
}

// ---------------- generic tiled SGEMM: out = act(A@W [+ A2@W2] [+ bias]) ----------------
// A [M,K] row-major, W [K,N] row-major, out [M,N]. BM=BN=64, BK=16, 256 threads, 4x4/thread.
template<bool HAS2, bool BIAS, bool RELU>
__global__ void sgemm_k(const float* __restrict__ A, const float* __restrict__ W,
                        const float* __restrict__ A2, const float* __restrict__ W2,
                        const float* __restrict__ bias, float* __restrict__ out,
                        int M, int K, int N) {
    __shared__ float As[16][65];
    __shared__ float Ws[16][64];
    int bm = blockIdx.y * 64, bn = blockIdx.x * 64;
    int t = threadIdx.x, tx = t & 15, ty = t >> 4;
    float acc[4][4] = {};

    #pragma unroll 1
    for (int srci = 0; srci < (HAS2 ? 2 : 1); ++srci) {
        const float* Ap = (HAS2 && srci) ? A2 : A;
        const float* Wp = (HAS2 && srci) ? W2 : W;
        for (int k0 = 0; k0 < K; k0 += 16) {
            #pragma unroll
            for (int i = 0; i < 4; i++) {
                int idx = t + i * 256;          // 0..1023 over [m][k]
                int m = idx >> 4, k = idx & 15;
                int row = bm + m;
                As[k][m] = (row < M) ? Ap[(size_t)row * K + k0 + k] : 0.f;
            }
            #pragma unroll
            for (int i = 0; i < 4; i++) {
                int idx = t + i * 256;          // [k][n]
                int k = idx >> 6, n = idx & 63;
                Ws[k][n] = Wp[(size_t)(k0 + k) * N + bn + n];
            }
            __syncthreads();
            #pragma unroll
            for (int k = 0; k < 16; k++) {
                // A tile has 65-float row stride (260B): NOT 16B aligned for
                // odd k, so read scalars (LDS.32). W tile stride is 256B so
                // float4 (LDS.128) is legal there.
                float av[4], bv[4];
                #pragma unroll
                for (int r = 0; r < 4; r++) av[r] = As[k][ty * 4 + r];
                float4 b = *(const float4*)&Ws[k][tx * 4];
                bv[0] = b.x; bv[1] = b.y; bv[2] = b.z; bv[3] = b.w;
                #pragma unroll
                for (int r = 0; r < 4; r++)
                    #pragma unroll
                    for (int c = 0; c < 4; c++)
                        acc[r][c] += av[r] * bv[c];
            }
            __syncthreads();
        }
    }
    #pragma unroll
    for (int r = 0; r < 4; r++) {
        int row = bm + ty * 4 + r;
        if (row >= M) continue;
        #pragma unroll
        for (int c = 0; c < 4; c++) {
            int col = bn + tx * 4 + c;
            float v = acc[r][c];
            if (BIAS) v += bias[col];
            if (RELU) v = fmaxf(v, 0.f);
            out[(size_t)row * N + col] = v;
        }
    }
}

// ---------------- segment max scatter (post-ReLU values are >= 0, so int atomicMax works) ----
template<int D>  // D = feature dim (128 or 256); thread handles 4 feats of one edge
__global__ void scatter_max_k(const float* __restrict__ msg, const int* __restrict__ src,
                              const int* __restrict__ dst, float* __restrict__ agg) {
    const int TPE = D / 4;  // threads per edge
    long long gtid = (long long)blockIdx.x * blockDim.x + threadIdx.x;
    int e = (int)(gtid / TPE);
    if (e >= EE) return;
    int f = ((int)(gtid % TPE)) * 4;
    int s = src[e], d = dst[e];
    float4 v = *(const float4*)(msg + (size_t)s * D + f);
    int* p = (int*)(agg + (size_t)d * D + f);
    atomicMax(p + 0, __float_as_int(v.x));
    atomicMax(p + 1, __float_as_int(v.y));
    atomicMax(p + 2, __float_as_int(v.z));
    atomicMax(p + 3, __float_as_int(v.w));
}

// ---------------- node head: node_pred = LN(h1@npW + npb); cls = softmax(node_pred) --------
__global__ void node_head_k(const float* __restrict__ h1, const float* __restrict__ npW,
                            const float* __restrict__ npb, const float* __restrict__ g,
                            const float* __restrict__ beta, float* __restrict__ node_pred,
                            float* __restrict__ cls) {
    int warp = (blockIdx.x * blockDim.x + threadIdx.x) >> 5;
    int lane = threadIdx.x & 31;
    if (warp >= NN) return;
    const float* row = h1 + (size_t)warp * D_HID;
    float p[5] = {};
    for (int k = lane; k < D_HID; k += 32) {
        float hv = row[k];
        #pragma unroll
        for (int j = 0; j < 5; j++) p[j] += hv * npW[k * 5 + j];
    }
    #pragma unroll
    for (int off = 16; off; off >>= 1)
        #pragma unroll
        for (int j = 0; j < 5; j++) p[j] += __shfl_xor_sync(0xffffffffu, p[j], off);
    #pragma unroll
    for (int j = 0; j < 5; j++) p[j] += npb[j];
    // LayerNorm over 5
    float mu = (p[0] + p[1] + p[2] + p[3] + p[4]) * 0.2f;
    float var = 0.f;
    #pragma unroll
    for (int j = 0; j < 5; j++) { float t = p[j] - mu; var += t * t; }
    var *= 0.2f;
    float inv = rsqrtf(var + EPS);
    float y[5];
    #pragma unroll
    for (int j = 0; j < 5; j++) y[j] = g[j] * (p[j] - mu) * inv + beta[j];
    // softmax
    float mx = y[0];
    #pragma unroll
    for (int j = 1; j < 5; j++) mx = fmaxf(mx, y[j]);
    float es[5], se = 0.f;
    #pragma unroll
    for (int j = 0; j < 5; j++) { es[j] = __expf(y[j] - mx); se += es[j]; }
    float rse = 1.f / se;
    if (lane == 0) {
        #pragma unroll
        for (int j = 0; j < 5; j++) {
            node_pred[(size_t)warp * 5 + j] = y[j];
            cls[(size_t)warp * 5 + j] = es[j] * rse;
        }
    }
}

// ---------------- edge head: warp per edge ----------------
// y = P[src] + Q[dst] + b1 + sum_i c16[i]*W1row_i ; LN ; relu ; @W2 + b2
__global__ void edge_head_k(const float* __restrict__ P, const float* __restrict__ Q,
                            const float* __restrict__ cls, const float* __restrict__ efeat,
                            const int* __restrict__ src, const int* __restrict__ dst,
                            const float* __restrict__ W1, const float* __restrict__ b1,
                            const float* __restrict__ g, const float* __restrict__ beta,
                            const float* __restrict__ W2, const float* __restrict__ b2,
                            float* __restrict__ out) {
    __shared__ __align__(16) float ws[16][256];
    for (int i = threadIdx.x; i < 16 * 256; i += blockDim.x) {
        int r = i >> 8, c = i & 255;
        int row = (r < 11) ? (256 + r) : (523 + r - 11);  // cls_src(5), efeat(6), cls_dst(5)
        ws[r][c] = W1[row * 256 + c];
    }
    __syncthreads();
    int e = blockIdx.x * 8 + (threadIdx.x >> 5);
    if (e >= EE) return;
    int lane = threadIdx.x & 31;
    int s = src[e], d = dst[e];
    int f0 = lane * 8;
    float y[8];
    {
        float4 pa = *(const float4*)(P + (size_t)s * 256 + f0);
        float4 pb = *(const float4*)(P + (size_t)s * 256 + f0 + 4);
        float4 qa = *(const float4*)(Q + (size_t)d * 256 + f0);
        float4 qb = *(const float4*)(Q + (size_t)d * 256 + f0 + 4);
        float4 ba = *(const float4*)(b1 + f0);
        float4 bb = *(const float4*)(b1 + f0 + 4);
        y[0] = pa.x + qa.x + ba.x; y[1] = pa.y + qa.y + ba.y;
        y[2] = pa.z + qa.z + ba.z; y[3] = pa.w + qa.w + ba.w;
        y[4] = pb.x + qb.x + bb.x; y[5] = pb.y + qb.y + bb.y;
        y[6] = pb.z + qb.z + bb.z; y[7] = pb.w + qb.w + bb.w;
    }
    float c16[16];
    #pragma unroll
    for (int i = 0; i < 5; i++) c16[i] = cls[(size_t)s * 5 + i];
    #pragma unroll
    for (int i = 0; i < 6; i++) c16[5 + i] = efeat[(size_t)e * 6 + i];
    #pragma unroll
    for (int i = 0; i < 5; i++) c16[11 + i] = cls[(size_t)d * 5 + i];
    #pragma unroll
    for (int i = 0; i < 16; i++) {
        float4 wa = *(const float4*)&ws[i][f0];
        float4 wb = *(const float4*)&ws[i][f0 + 4];
        float ci = c16[i];
        y[0] += ci * wa.x; y[1] += ci * wa.y; y[2] += ci * wa.z; y[3] += ci * wa.w;
        y[4] += ci * wb.x; y[5] += ci * wb.y; y[6] += ci * wb.z; y[7] += ci * wb.w;
    }
    // LayerNorm over 256
    float sum = 0.f;
    #pragma unroll
    for (int i = 0; i < 8; i++) sum += y[i];
    #pragma unroll
    for (int off = 16; off; off >>= 1) sum += __shfl_xor_sync(0xffffffffu, sum, off);
    float mu = sum * (1.f / 256.f);
    float vs = 0.f;
    #pragma unroll
    for (int i = 0; i < 8; i++) { float t = y[i] - mu; vs += t * t; }
    #pragma unroll
    for (int off = 16; off; off >>= 1) vs += __shfl_xor_sync(0xffffffffu, vs, off);
    float inv = rsqrtf(vs * (1.f / 256.f) + EPS);
    float o0 = 0.f, o1 = 0.f;
    #pragma unroll
    for (int i = 0; i < 8; i++) {
        int f = f0 + i;
        float yn = g[f] * (y[i] - mu) * inv + beta[f];
        yn = fmaxf(yn, 0.f);
        o0 += yn * W2[f * 2 + 0];
        o1 += yn * W2[f * 2 + 1];
    }
    #pragma unroll
    for (int off = 16; off; off >>= 1) {
        o0 += __shfl_xor_sync(0xffffffffu, o0, off);
        o1 += __shfl_xor_sync(0xffffffffu, o1, off);
    }
    if (lane == 0) {
        out[(size_t)e * 2 + 0] = o0 + b2[0];
        out[(size_t)e * 2 + 1] = o1 + b2[1];
    }
}

// ---------------- launch ----------------
extern "C" void kernel_launch(void* const* d_in, const int* in_sizes, int n_in,
                              void* d_out, int out_size) {
    const float* h        = (const float*)d_in[0];
    const float* efeat    = (const float*)d_in[1];
    const int*   src      = (const int*)  d_in[2];
    const int*   dst      = (const int*)  d_in[3];
    const float* encWpool = (const float*)d_in[4];
    const float* encbpool = (const float*)d_in[5];
    const float* encWself = (const float*)d_in[6];
    const float* encbself = (const float*)d_in[7];
    const float* encWneigh= (const float*)d_in[8];
    const float* npW      = (const float*)d_in[9];
    const float* npb      = (const float*)d_in[10];
    const float* npg      = (const float*)d_in[11];
    const float* npbeta   = (const float*)d_in[12];
    const float* epW1     = (const float*)d_in[13];
    const float* epb1     = (const float*)d_in[14];
    const float* epg      = (const float*)d_in[15];
    const float* epbeta   = (const float*)d_in[16];
    const float* epW2     = (const float*)d_in[17];
    const float* epb2     = (const float*)d_in[18];
    const float* decWpool = (const float*)d_in[19];
    const float* decbpool = (const float*)d_in[20];
    const float* decWself = (const float*)d_in[21];
    const float* decbself = (const float*)d_in[22];
    const float* decWneigh= (const float*)d_in[23];

    float* out       = (float*)d_out;
    float* node_pred = out;                       // [NN,5]
    float* edge_pred = out + NN * 5;              // [EE,2]
    float* h2        = out + NN * 5 + EE * 2;     // [NN,128]

    float *m1, *agg1, *h1, *cls, *P, *Q, *m2, *agg2;
    cudaGetSymbolAddress((void**)&m1,  g_m1);
    cudaGetSymbolAddress((void**)&agg1,g_agg1);
    cudaGetSymbolAddress((void**)&h1,  g_h1);
    cudaGetSymbolAddress((void**)&cls, g_cls);
    cudaGetSymbolAddress((void**)&P,   g_P);
    cudaGetSymbolAddress((void**)&Q,   g_Q);
    cudaGetSymbolAddress((void**)&m2,  g_m2);
    cudaGetSymbolAddress((void**)&agg2,g_agg2);

    int mblocks = (NN + 63) / 64;   // 469

    zero_aggs<<<512, 256>>>();

    // encoder: m1 = relu(h @ encWpool + bpool)   [30000,128]x[128,128]
    sgemm_k<false, true, true><<<dim3(D_IN / 64, mblocks), 256>>>(
        h, encWpool, nullptr, nullptr, encbpool, m1, NN, D_IN, D_IN);

    // encoder segment max
    {
        long long tot = (long long)EE * (D_IN / 4);
        scatter_max_k<D_IN><<<(unsigned)((tot + 255) / 256), 256>>>(m1, src, dst, agg1);
    }

    // h1 = relu(h@Wself + agg1@Wneigh + bself)   -> [30000,256]
    sgemm_k<true, true, true><<<dim3(D_HID / 64, mblocks), 256>>>(
        h, encWself, agg1, encWneigh, encbself, h1, NN, D_IN, D_HID);

    // node head
    node_head_k<<<(NN * 32 + 255) / 256, 256>>>(h1, npW, npb, npg, npbeta, node_pred, cls);

    // P = h1 @ W1[0:256,:], Q = h1 @ W1[267:523,:]
    sgemm_k<false, false, false><<<dim3(D_HID / 64, mblocks), 256>>>(
        h1, epW1, nullptr, nullptr, nullptr, P, NN, D_HID, D_HID);
    sgemm_k<false, false, false><<<dim3(D_HID / 64, mblocks), 256>>>(
        h1, epW1 + 267 * 256, nullptr, nullptr, nullptr, Q, NN, D_HID, D_HID);

    // edge head
    edge_head_k<<<(EE + 7) / 8, 256>>>(P, Q, cls, efeat, src, dst,
                                       epW1, epb1, epg, epbeta, epW2, epb2, edge_pred);

    // decoder: m2 = relu(h1 @ decWpool + bpool)  [30000,256]x[256,256]
    sgemm_k<false, true, true><<<dim3(D_HID / 64, mblocks), 256>>>(
        h1, decWpool, nullptr, nullptr, decbpool, m2, NN, D_HID, D_HID);

    // decoder segment max
    {
        long long tot = (long long)EE * (D_HID / 4);
        scatter_max_k<D_HID><<<(unsigned)((tot + 255) / 256), 256>>>(m2, src, dst, agg2);
    }

    // h2 = relu(h1@decWself + agg2@decWneigh + bself) -> [30000,128]
    sgemm_k<true, true, true><<<dim3(D_IN / 64, mblocks), 256>>>(
        h1, decWself, agg2, decWneigh, decbself, h2, NN, D_HID, D_IN);
}

// round 3
// speedup vs baseline: 1.1840x; 1.1840x over previous
#include <cuda_runtime.h>
#include <cuda_bf16.h>
#include <math.h>

#define NN 30000
#define EE 480000
#define D_IN 128
#define D_HID 256
#define EPS 1e-5f

// ---------------- scratch (device globals; no allocation) ----------------
__device__ float g_m1 [NN * D_IN];    // encoder pool messages
__device__ float g_agg1[NN * D_IN];   // encoder segment-max
__device__ float g_h1 [NN * D_HID];   // encoder output
__device__ float g_cls[NN * 5];       // softmax(node_pred)
__device__ float g_P  [NN * D_HID];   // h1 @ W1[0:256]
__device__ float g_Q  [NN * D_HID];   // h1 @ W1[267:523]
__device__ float g_m2 [NN * D_HID];   // decoder pool messages
__device__ float g_agg2[NN * D_HID];  // decoder segment-max
// CSR by dst (graph is reused by both SAGE layers)
__device__ int g_deg [NN];
__device__ int g_cur [NN];
__device__ int g_rowstart[NN + 1];
__device__ int g_csrc[EE];

// ---------------- CSR build ----------------
__global__ void csr_zero_k() {
    int i = blockIdx.x * blockDim.x + threadIdx.x;
    if (i < NN) { g_deg[i] = 0; g_cur[i] = 0; }
}
__global__ void csr_hist_k(const int* __restrict__ dst) {
    int e = blockIdx.x * blockDim.x + threadIdx.x;
    if (e < EE) atomicAdd(&g_deg[dst[e]], 1);
}
__global__ void csr_scan_k() {   // single block, 1024 threads
    __shared__ int s[1024];
    int t = threadIdx.x;
    const int C = (NN + 1023) / 1024;   // 30
    int base = t * C;
    int sum = 0;
    for (int i = 0; i < C; i++) { int idx = base + i; if (idx < NN) sum += g_deg[idx]; }
    s[t] = sum; __syncthreads();
    for (int off = 1; off < 1024; off <<= 1) {
        int v = (t >= off) ? s[t - off] : 0;
        __syncthreads();
        s[t] += v;
        __syncthreads();
    }
    int run = (t > 0) ? s[t - 1] : 0;
    for (int i = 0; i < C; i++) {
        int idx = base + i;
        if (idx < NN) { g_rowstart[idx] = run; run += g_deg[idx]; }
    }
    if (t == 1023) g_rowstart[NN] = EE;
}
__global__ void csr_fill_k(const int* __restrict__ src, const int* __restrict__ dst) {
    int e = blockIdx.x * blockDim.x + threadIdx.x;
    if (e >= EE) return;
    int d = dst[e];
    int pos = atomicAdd(&g_cur[d], 1);
    g_csrc[g_rowstart[d] + pos] = src[e];
}

// ---------------- gather segment-max (messages are post-ReLU >= 0 so init 0 is exact) ----
__global__ void gather_max_128(const float* __restrict__ msg, float* __restrict__ agg) {
    int warp = (blockIdx.x * blockDim.x + threadIdx.x) >> 5;
    int lane = threadIdx.x & 31;
    if (warp >= NN) return;
    int rs = g_rowstart[warp], re = g_rowstart[warp + 1];
    float4 v = make_float4(0.f, 0.f, 0.f, 0.f);
    for (int j = rs; j < re; j++) {
        int s = g_csrc[j];
        float4 m = *(const float4*)(msg + (size_t)s * 128 + lane * 4);
        v.x = fmaxf(v.x, m.x); v.y = fmaxf(v.y, m.y);
        v.z = fmaxf(v.z, m.z); v.w = fmaxf(v.w, m.w);
    }
    *(float4*)(agg + (size_t)warp * 128 + lane * 4) = v;
}
__global__ void gather_max_256(const float* __restrict__ msg, float* __restrict__ agg) {
    int warp = (blockIdx.x * blockDim.x + threadIdx.x) >> 5;
    int lane = threadIdx.x & 31;
    if (warp >= NN) return;
    int rs = g_rowstart[warp], re = g_rowstart[warp + 1];
    float4 v0 = make_float4(0.f, 0.f, 0.f, 0.f);
    float4 v1 = v0;
    for (int j = rs; j < re; j++) {
        int s = g_csrc[j];
        const float* row = msg + (size_t)s * 256;
        float4 a = *(const float4*)(row + lane * 4);
        float4 b = *(const float4*)(row + 128 + lane * 4);
        v0.x = fmaxf(v0.x, a.x); v0.y = fmaxf(v0.y, a.y);
        v0.z = fmaxf(v0.z, a.z); v0.w = fmaxf(v0.w, a.w);
        v1.x = fmaxf(v1.x, b.x); v1.y = fmaxf(v1.y, b.y);
        v1.z = fmaxf(v1.z, b.z); v1.w = fmaxf(v1.w, b.w);
    }
    *(float4*)(agg + (size_t)warp * 256 + lane * 4) = v0;
    *(float4*)(agg + (size_t)warp * 256 + 128 + lane * 4) = v1;
}

// ---------------- SGEMM 128x128x8, 8x8/thread, all-float4 smem ----------------
// out = act(A@W [+ A2@W2] [+ bias]);  A [M,K], W [K,N] row-major. K % 8 == 0, N % 128 == 0.
template<bool HAS2, bool BIAS, bool RELU>
__global__ __launch_bounds__(256) void sgemm128(
        const float* __restrict__ A, const float* __restrict__ W,
        const float* __restrict__ A2, const float* __restrict__ W2,
        const float* __restrict__ bias, float* __restrict__ out,
        int M, int K, int N) {
    __shared__ __align__(16) float As[8][132];   // [k][m], 132*4=528B stride (16B multiple)
    __shared__ __align__(16) float Ws[8][132];   // [k][n]
    int bm = blockIdx.y * 128, bn = blockIdx.x * 128;
    int t = threadIdx.x;
    int tx = t & 15, ty = t >> 4;         // 16 x 16 thread grid; 8x8 each
    // load mapping
    int a_row = t >> 1, a_k = (t & 1) * 4;            // A: float4 along K
    int w_k = t >> 5, w_n = (t & 31) * 4;             // W: float4 along N
    float acc[8][8] = {};

    #pragma unroll 1
    for (int srci = 0; srci < (HAS2 ? 2 : 1); ++srci) {
        const float* Ap = (HAS2 && srci) ? A2 : A;
        const float* Wp = (HAS2 && srci) ? W2 : W;
        for (int k0 = 0; k0 < K; k0 += 8) {
            int arow = bm + a_row;
            float4 av4 = make_float4(0.f, 0.f, 0.f, 0.f);
            if (arow < M) av4 = *(const float4*)(Ap + (size_t)arow * K + k0 + a_k);
            float4 wv4 = *(const float4*)(Wp + (size_t)(k0 + w_k) * N + bn + w_n);
            __syncthreads();
            As[a_k + 0][a_row] = av4.x;
            As[a_k + 1][a_row] = av4.y;
            As[a_k + 2][a_row] = av4.z;
            As[a_k + 3][a_row] = av4.w;
            *(float4*)&Ws[w_k][w_n] = wv4;
            __syncthreads();
            #pragma unroll
            for (int k = 0; k < 8; k++) {
                float4 a0 = *(const float4*)&As[k][ty * 8];
                float4 a1 = *(const float4*)&As[k][ty * 8 + 4];
                float4 b0 = *(const float4*)&Ws[k][tx * 8];
                float4 b1 = *(const float4*)&Ws[k][tx * 8 + 4];
                float av[8] = {a0.x, a0.y, a0.z, a0.w, a1.x, a1.y, a1.z, a1.w};
                float bv[8] = {b0.x, b0.y, b0.z, b0.w, b1.x, b1.y, b1.z, b1.w};
                #pragma unroll
                for (int r = 0; r < 8; r++)
                    #pragma unroll
                    for (int c = 0; c < 8; c++)
                        acc[r][c] += av[r] * bv[c];
            }
        }
    }
    #pragma unroll
    for (int r = 0; r < 8; r++) {
        int row = bm + ty * 8 + r;
        if (row >= M) continue;
        #pragma unroll
        for (int c4 = 0; c4 < 2; c4++) {
            int col = bn + tx * 8 + c4 * 4;
            float4 v;
            v.x = acc[r][c4 * 4 + 0]; v.y = acc[r][c4 * 4 + 1];
            v.z = acc[r][c4 * 4 + 2]; v.w = acc[r][c4 * 4 + 3];
            if (BIAS) {
                float4 bb = *(const float4*)(bias + col);
                v.x += bb.x; v.y += bb.y; v.z += bb.z; v.w += bb.w;
            }
            if (RELU) {
                v.x = fmaxf(v.x, 0.f); v.y = fmaxf(v.y, 0.f);
                v.z = fmaxf(v.z, 0.f); v.w = fmaxf(v.w, 0.f);
            }
            *(float4*)(out + (size_t)row * N + col) = v;
        }
    }
}

// ---------------- node head: node_pred = LN(h1@npW + npb); cls = softmax(node_pred) --------
__global__ void node_head_k(const float* __restrict__ h1, const float* __restrict__ npW,
                            const float* __restrict__ npb, const float* __restrict__ g,
                            const float* __restrict__ beta, float* __restrict__ node_pred,
                            float* __restrict__ cls) {
    int warp = (blockIdx.x * blockDim.x + threadIdx.x) >> 5;
    int lane = threadIdx.x & 31;
    if (warp >= NN) return;
    const float* row = h1 + (size_t)warp * D_HID;
    float p[5] = {};
    for (int k = lane; k < D_HID; k += 32) {
        float hv = row[k];
        #pragma unroll
        for (int j = 0; j < 5; j++) p[j] += hv * npW[k * 5 + j];
    }
    #pragma unroll
    for (int off = 16; off; off >>= 1)
        #pragma unroll
        for (int j = 0; j < 5; j++) p[j] += __shfl_xor_sync(0xffffffffu, p[j], off);
    #pragma unroll
    for (int j = 0; j < 5; j++) p[j] += npb[j];
    float mu = (p[0] + p[1] + p[2] + p[3] + p[4]) * 0.2f;
    float var = 0.f;
    #pragma unroll
    for (int j = 0; j < 5; j++) { float t = p[j] - mu; var += t * t; }
    var *= 0.2f;
    float inv = rsqrtf(var + EPS);
    float y[5];
    #pragma unroll
    for (int j = 0; j < 5; j++) y[j] = g[j] * (p[j] - mu) * inv + beta[j];
    float mx = y[0];
    #pragma unroll
    for (int j = 1; j < 5; j++) mx = fmaxf(mx, y[j]);
    float es[5], se = 0.f;
    #pragma unroll
    for (int j = 0; j < 5; j++) { es[j] = __expf(y[j] - mx); se += es[j]; }
    float rse = 1.f / se;
    if (lane == 0) {
        #pragma unroll
        for (int j = 0; j < 5; j++) {
            node_pred[(size_t)warp * 5 + j] = y[j];
            cls[(size_t)warp * 5 + j] = es[j] * rse;
        }
    }
}

// ---------------- edge head: warp per edge ----------------
__global__ void edge_head_k(const float* __restrict__ P, const float* __restrict__ Q,
                            const float* __restrict__ cls, const float* __restrict__ efeat,
                            const int* __restrict__ src, const int* __restrict__ dst,
                            const float* __restrict__ W1, const float* __restrict__ b1,
                            const float* __restrict__ g, const float* __restrict__ beta,
                            const float* __restrict__ W2, const float* __restrict__ b2,
                            float* __restrict__ out) {
    __shared__ __align__(16) float ws[16][256];
    for (int i = threadIdx.x; i < 16 * 256; i += blockDim.x) {
        int r = i >> 8, c = i & 255;
        int row = (r < 11) ? (256 + r) : (523 + r - 11);  // cls_src(5), efeat(6), cls_dst(5)
        ws[r][c] = W1[row * 256 + c];
    }
    __syncthreads();
    int e = blockIdx.x * 8 + (threadIdx.x >> 5);
    if (e >= EE) return;
    int lane = threadIdx.x & 31;
    int s = src[e], d = dst[e];
    int f0 = lane * 8;
    float y[8];
    {
        float4 pa = *(const float4*)(P + (size_t)s * 256 + f0);
        float4 pb = *(const float4*)(P + (size_t)s * 256 + f0 + 4);
        float4 qa = *(const float4*)(Q + (size_t)d * 256 + f0);
        float4 qb = *(const float4*)(Q + (size_t)d * 256 + f0 + 4);
        float4 ba = *(const float4*)(b1 + f0);
        float4 bb = *(const float4*)(b1 + f0 + 4);
        y[0] = pa.x + qa.x + ba.x; y[1] = pa.y + qa.y + ba.y;
        y[2] = pa.z + qa.z + ba.z; y[3] = pa.w + qa.w + ba.w;
        y[4] = pb.x + qb.x + bb.x; y[5] = pb.y + qb.y + bb.y;
        y[6] = pb.z + qb.z + bb.z; y[7] = pb.w + qb.w + bb.w;
    }
    float c16[16];
    #pragma unroll
    for (int i = 0; i < 5; i++) c16[i] = cls[(size_t)s * 5 + i];
    #pragma unroll
    for (int i = 0; i < 6; i++) c16[5 + i] = efeat[(size_t)e * 6 + i];
    #pragma unroll
    for (int i = 0; i < 5; i++) c16[11 + i] = cls[(size_t)d * 5 + i];
    #pragma unroll
    for (int i = 0; i < 16; i++) {
        float4 wa = *(const float4*)&ws[i][f0];
        float4 wb = *(const float4*)&ws[i][f0 + 4];
        float ci = c16[i];
        y[0] += ci * wa.x; y[1] += ci * wa.y; y[2] += ci * wa.z; y[3] += ci * wa.w;
        y[4] += ci * wb.x; y[5] += ci * wb.y; y[6] += ci * wb.z; y[7] += ci * wb.w;
    }
    float sum = 0.f;
    #pragma unroll
    for (int i = 0; i < 8; i++) sum += y[i];
    #pragma unroll
    for (int off = 16; off; off >>= 1) sum += __shfl_xor_sync(0xffffffffu, sum, off);
    float mu = sum * (1.f / 256.f);
    float vs = 0.f;
    #pragma unroll
    for (int i = 0; i < 8; i++) { float t = y[i] - mu; vs += t * t; }
    #pragma unroll
    for (int off = 16; off; off >>= 1) vs += __shfl_xor_sync(0xffffffffu, vs, off);
    float inv = rsqrtf(vs * (1.f / 256.f) + EPS);
    float o0 = 0.f, o1 = 0.f;
    #pragma unroll
    for (int i = 0; i < 8; i++) {
        int f = f0 + i;
        float yn = g[f] * (y[i] - mu) * inv + beta[f];
        yn = fmaxf(yn, 0.f);
        o0 += yn * W2[f * 2 + 0];
        o1 += yn * W2[f * 2 + 1];
    }
    #pragma unroll
    for (int off = 16; off; off >>= 1) {
        o0 += __shfl_xor_sync(0xffffffffu, o0, off);
        o1 += __shfl_xor_sync(0xffffffffu, o1, off);
    }
    if (lane == 0) {
        out[(size_t)e * 2 + 0] = o0 + b2[0];
        out[(size_t)e * 2 + 1] = o1 + b2[1];
    }
}

// ---------------- launch ----------------
extern "C" void kernel_launch(void* const* d_in, const int* in_sizes, int n_in,
                              void* d_out, int out_size) {
    const float* h        = (const float*)d_in[0];
    const float* efeat    = (const float*)d_in[1];
    const int*   src      = (const int*)  d_in[2];
    const int*   dst      = (const int*)  d_in[3];
    const float* encWpool = (const float*)d_in[4];
    const float* encbpool = (const float*)d_in[5];
    const float* encWself = (const float*)d_in[6];
    const float* encbself = (const float*)d_in[7];
    const float* encWneigh= (const float*)d_in[8];
    const float* npW      = (const float*)d_in[9];
    const float* npb      = (const float*)d_in[10];
    const float* npg      = (const float*)d_in[11];
    const float* npbeta   = (const float*)d_in[12];
    const float* epW1     = (const float*)d_in[13];
    const float* epb1     = (const float*)d_in[14];
    const float* epg      = (const float*)d_in[15];
    const float* epbeta   = (const float*)d_in[16];
    const float* epW2     = (const float*)d_in[17];
    const float* epb2     = (const float*)d_in[18];
    const float* decWpool = (const float*)d_in[19];
    const float* decbpool = (const float*)d_in[20];
    const float* decWself = (const float*)d_in[21];
    const float* decbself = (const float*)d_in[22];
    const float* decWneigh= (const float*)d_in[23];

    float* out       = (float*)d_out;
    float* node_pred = out;                       // [NN,5]
    float* edge_pred = out + NN * 5;              // [EE,2]
    float* h2        = out + NN * 5 + EE * 2;     // [NN,128]

    float *m1, *agg1, *h1, *cls, *P, *Q, *m2, *agg2;
    cudaGetSymbolAddress((void**)&m1,  g_m1);
    cudaGetSymbolAddress((void**)&agg1,g_agg1);
    cudaGetSymbolAddress((void**)&h1,  g_h1);
    cudaGetSymbolAddress((void**)&cls, g_cls);
    cudaGetSymbolAddress((void**)&P,   g_P);
    cudaGetSymbolAddress((void**)&Q,   g_Q);
    cudaGetSymbolAddress((void**)&m2,  g_m2);
    cudaGetSymbolAddress((void**)&agg2,g_agg2);

    int mb128 = (NN + 127) / 128;   // 235

    // CSR build (shared by both SAGE layers)
    csr_zero_k<<<(NN + 255) / 256, 256>>>();
    csr_hist_k<<<(EE + 255) / 256, 256>>>(dst);
    csr_scan_k<<<1, 1024>>>();
    csr_fill_k<<<(EE + 255) / 256, 256>>>(src, dst);

    // encoder: m1 = relu(h @ encWpool + bpool)   [30000,128]x[128,128]
    sgemm128<false, true, true><<<dim3(1, mb128), 256>>>(
        h, encWpool, nullptr, nullptr, encbpool, m1, NN, D_IN, D_IN);

    // encoder segment max (gather)
    gather_max_128<<<(NN * 32 + 255) / 256, 256>>>(m1, agg1);

    // h1 = relu(h@Wself + agg1@Wneigh + bself)   -> [30000,256]
    sgemm128<true, true, true><<<dim3(2, mb128), 256>>>(
        h, encWself, agg1, encWneigh, encbself, h1, NN, D_IN, D_HID);

    // node head
    node_head_k<<<(NN * 32 + 255) / 256, 256>>>(h1, npW, npb, npg, npbeta, node_pred, cls);

    // P = h1 @ W1[0:256,:], Q = h1 @ W1[267:523,:]
    sgemm128<false, false, false><<<dim3(2, mb128), 256>>>(
        h1, epW1, nullptr, nullptr, nullptr, P, NN, D_HID, D_HID);
    sgemm128<false, false, false><<<dim3(2, mb128), 256>>>(
        h1, epW1 + 267 * 256, nullptr, nullptr, nullptr, Q, NN, D_HID, D_HID);

    // edge head
    edge_head_k<<<(EE + 7) / 8, 256>>>(P, Q, cls, efeat, src, dst,
                                       epW1, epb1, epg, epbeta, epW2, epb2, edge_pred);

    // decoder: m2 = relu(h1 @ decWpool + bpool)  [30000,256]x[256,256]
    sgemm128<false, true, true><<<dim3(2, mb128), 256>>>(
        h1, decWpool, nullptr, nullptr, decbpool, m2, NN, D_HID, D_HID);

    // decoder segment max (gather)
    gather_max_256<<<(NN * 32 + 255) / 256, 256>>>(m2, agg2);

    // h2 = relu(h1@decWself + agg2@decWneigh + bself) -> [30000,128]
    sgemm128<true, true, true><<<dim3(1, mb128), 256>>>(
        h1, decWself, agg2, decWneigh, decbself, h2, NN, D_HID, D_IN);
}

// round 4
// speedup vs baseline: 1.5262x; 1.2890x over previous
#include <cuda_runtime.h>
#include <cuda_bf16.h>
#include <math.h>

#define NN 30000
#define EE 480000
#define D_IN 128
#define D_HID 256
#define EPS 1e-5f

// ---------------- scratch (device globals; no allocation) ----------------
__device__ float g_m1 [NN * D_IN];
__device__ float g_agg1[NN * D_IN];
__device__ float g_h1 [NN * D_HID];
__device__ float g_cls[NN * 5];
__device__ float g_P  [NN * D_HID];
__device__ float g_Q  [NN * D_HID];
__device__ float g_m2 [NN * D_HID];
__device__ float g_agg2[NN * D_HID];
__device__ int g_deg [NN];
__device__ int g_cur [NN];
__device__ int g_rowstart[NN + 1];
__device__ int g_csrc[EE];

// ---------------- CSR build ----------------
__global__ void csr_zero_k() {
    int i = blockIdx.x * blockDim.x + threadIdx.x;
    if (i < NN) { g_deg[i] = 0; g_cur[i] = 0; }
}
__global__ void csr_hist_k(const int* __restrict__ dst) {
    int e = blockIdx.x * blockDim.x + threadIdx.x;
    if (e < EE) atomicAdd(&g_deg[dst[e]], 1);
}
__global__ void csr_scan_k() {
    __shared__ int s[1024];
    int t = threadIdx.x;
    const int C = (NN + 1023) / 1024;
    int base = t * C;
    int sum = 0;
    for (int i = 0; i < C; i++) { int idx = base + i; if (idx < NN) sum += g_deg[idx]; }
    s[t] = sum; __syncthreads();
    for (int off = 1; off < 1024; off <<= 1) {
        int v = (t >= off) ? s[t - off] : 0;
        __syncthreads();
        s[t] += v;
        __syncthreads();
    }
    int run = (t > 0) ? s[t - 1] : 0;
    for (int i = 0; i < C; i++) {
        int idx = base + i;
        if (idx < NN) { g_rowstart[idx] = run; run += g_deg[idx]; }
    }
    if (t == 1023) g_rowstart[NN] = EE;
}
__global__ void csr_fill_k(const int* __restrict__ src, const int* __restrict__ dst) {
    int e = blockIdx.x * blockDim.x + threadIdx.x;
    if (e >= EE) return;
    int d = dst[e];
    int pos = atomicAdd(&g_cur[d], 1);
    g_csrc[g_rowstart[d] + pos] = src[e];
}

// ---------------- gather segment-max ----------------
__global__ void gather_max_128(const float* __restrict__ msg, float* __restrict__ agg) {
    int warp = (blockIdx.x * blockDim.x + threadIdx.x) >> 5;
    int lane = threadIdx.x & 31;
    if (warp >= NN) return;
    int rs = g_rowstart[warp], re = g_rowstart[warp + 1];
    float4 v = make_float4(0.f, 0.f, 0.f, 0.f);
    for (int j = rs; j < re; j++) {
        int s = g_csrc[j];
        float4 m = *(const float4*)(msg + (size_t)s * 128 + lane * 4);
        v.x = fmaxf(v.x, m.x); v.y = fmaxf(v.y, m.y);
        v.z = fmaxf(v.z, m.z); v.w = fmaxf(v.w, m.w);
    }
    *(float4*)(agg + (size_t)warp * 128 + lane * 4) = v;
}
__global__ void gather_max_256(const float* __restrict__ msg, float* __restrict__ agg) {
    int warp = (blockIdx.x * blockDim.x + threadIdx.x) >> 5;
    int lane = threadIdx.x & 31;
    if (warp >= NN) return;
    int rs = g_rowstart[warp], re = g_rowstart[warp + 1];
    float4 v0 = make_float4(0.f, 0.f, 0.f, 0.f);
    float4 v1 = v0;
    for (int j = rs; j < re; j++) {
        int s = g_csrc[j];
        const float* row = msg + (size_t)s * 256;
        float4 a = *(const float4*)(row + lane * 4);
        float4 b = *(const float4*)(row + 128 + lane * 4);
        v0.x = fmaxf(v0.x, a.x); v0.y = fmaxf(v0.y, a.y);
        v0.z = fmaxf(v0.z, a.z); v0.w = fmaxf(v0.w, a.w);
        v1.x = fmaxf(v1.x, b.x); v1.y = fmaxf(v1.y, b.y);
        v1.z = fmaxf(v1.z, b.z); v1.w = fmaxf(v1.w, b.w);
    }
    *(float4*)(agg + (size_t)warp * 256 + lane * 4) = v0;
    *(float4*)(agg + (size_t)warp * 256 + 128 + lane * 4) = v1;
}

// ---------------- tf32 tensor-core GEMM ----------------
// out = act(A@W [+ A2@W2] [+ bias]); A [M,K] rm, W [K,N] rm. K%32==0, N%128==0.
// Tile 128x128x32, 8 warps, warp tile 64x32 (4x4 m16n8k8 mma).
__device__ __forceinline__ unsigned f2tf32(float v) {
    unsigned r;
    asm("cvt.rna.tf32.f32 %0, %1;" : "=r"(r) : "f"(v));
    return r;
}
__device__ __forceinline__ void mma_tf32(float& c0, float& c1, float& c2, float& c3,
                                         unsigned a0, unsigned a1, unsigned a2, unsigned a3,
                                         unsigned b0, unsigned b1) {
    asm volatile("mma.sync.aligned.m16n8k8.row.col.f32.tf32.tf32.f32 "
                 "{%0,%1,%2,%3}, {%4,%5,%6,%7}, {%8,%9}, {%0,%1,%2,%3};"
                 : "+f"(c0), "+f"(c1), "+f"(c2), "+f"(c3)
                 : "r"(a0), "r"(a1), "r"(a2), "r"(a3), "r"(b0), "r"(b1));
}

#define AS_STRIDE 36   // banks (4g+q): conflict-free fragment LDS
#define BS_STRIDE 136  // banks (8q+g): conflict-free fragment LDS

template<bool HAS2, bool BIAS, bool RELU>
__global__ __launch_bounds__(256) void tgemm(
        const float* __restrict__ A, const float* __restrict__ W,
        const float* __restrict__ A2, const float* __restrict__ W2,
        const float* __restrict__ bias, float* __restrict__ out,
        int M, int K, int N) {
    __shared__ unsigned As[128 * AS_STRIDE];   // [m][k] as tf32 bits
    __shared__ unsigned Bs[32 * BS_STRIDE];    // [k][n] as tf32 bits
    int bm = blockIdx.y * 128, bn = blockIdx.x * 128;
    int t = threadIdx.x;
    int w = t >> 5, lane = t & 31;
    int g = lane >> 2, q = lane & 3;
    int wm = (w >> 2) * 64, wn = (w & 3) * 32;

    float acc[4][4][4];
    #pragma unroll
    for (int i = 0; i < 4; i++)
        #pragma unroll
        for (int j = 0; j < 4; j++)
            #pragma unroll
            for (int r = 0; r < 4; r++) acc[i][j][r] = 0.f;

    // load mapping: A: thread t -> row t>>3, k4=(t&7)*4, 4 row-phases of 32
    int a_row = t >> 3, a_k = (t & 7) * 4;
    // W: thread t -> k t>>5, n4=(t&31)*4, 4 k-phases of 8
    int w_k = t >> 5, w_n = (t & 31) * 4;

    #pragma unroll 1
    for (int srci = 0; srci < (HAS2 ? 2 : 1); ++srci) {
        const float* Ap = (HAS2 && srci) ? A2 : A;
        const float* Wp = (HAS2 && srci) ? W2 : W;
        for (int k0 = 0; k0 < K; k0 += 32) {
            __syncthreads();
            #pragma unroll
            for (int ph = 0; ph < 4; ph++) {
                int row = a_row + ph * 32;
                int grow = bm + row;
                float4 v = make_float4(0.f, 0.f, 0.f, 0.f);
                if (grow < M) v = *(const float4*)(Ap + (size_t)grow * K + k0 + a_k);
                unsigned* p = &As[row * AS_STRIDE + a_k];
                p[0] = f2tf32(v.x); p[1] = f2tf32(v.y);
                p[2] = f2tf32(v.z); p[3] = f2tf32(v.w);
            }
            #pragma unroll
            for (int ph = 0; ph < 4; ph++) {
                int kk = w_k + ph * 8;
                float4 v = *(const float4*)(Wp + (size_t)(k0 + kk) * N + bn + w_n);
                unsigned* p = &Bs[kk * BS_STRIDE + w_n];
                p[0] = f2tf32(v.x); p[1] = f2tf32(v.y);
                p[2] = f2tf32(v.z); p[3] = f2tf32(v.w);
            }
            __syncthreads();
            #pragma unroll
            for (int kk = 0; kk < 32; kk += 8) {
                unsigned af[4][4], bf[4][2];
                #pragma unroll
                for (int mi = 0; mi < 4; mi++) {
                    int r0 = wm + mi * 16 + g;
                    const unsigned* p = &As[r0 * AS_STRIDE + kk + q];
                    af[mi][0] = p[0];
                    af[mi][1] = p[8 * AS_STRIDE];
                    af[mi][2] = p[4];
                    af[mi][3] = p[8 * AS_STRIDE + 4];
                }
                #pragma unroll
                for (int ni = 0; ni < 4; ni++) {
                    int n = wn + ni * 8 + g;
                    const unsigned* p = &Bs[(kk + q) * BS_STRIDE + n];
                    bf[ni][0] = p[0];
                    bf[ni][1] = p[4 * BS_STRIDE];
                }
                #pragma unroll
                for (int mi = 0; mi < 4; mi++)
                    #pragma unroll
                    for (int ni = 0; ni < 4; ni++)
                        mma_tf32(acc[mi][ni][0], acc[mi][ni][1], acc[mi][ni][2], acc[mi][ni][3],
                                 af[mi][0], af[mi][1], af[mi][2], af[mi][3],
                                 bf[ni][0], bf[ni][1]);
            }
        }
    }

    // epilogue: c0,c1 -> (r0, col..col+1), c2,c3 -> (r0+8, col..col+1)
    #pragma unroll
    for (int mi = 0; mi < 4; mi++) {
        int r0 = bm + wm + mi * 16 + g;
        #pragma unroll
        for (int ni = 0; ni < 4; ni++) {
            int col = bn + wn + ni * 8 + q * 2;
            float b0 = 0.f, b1 = 0.f;
            if (BIAS) { b0 = bias[col]; b1 = bias[col + 1]; }
            float2 lo, hi;
            lo.x = acc[mi][ni][0] + b0; lo.y = acc[mi][ni][1] + b1;
            hi.x = acc[mi][ni][2] + b0; hi.y = acc[mi][ni][3] + b1;
            if (RELU) {
                lo.x = fmaxf(lo.x, 0.f); lo.y = fmaxf(lo.y, 0.f);
                hi.x = fmaxf(hi.x, 0.f); hi.y = fmaxf(hi.y, 0.f);
            }
            if (r0 < M)     *(float2*)(out + (size_t)r0 * N + col) = lo;
            if (r0 + 8 < M) *(float2*)(out + (size_t)(r0 + 8) * N + col) = hi;
        }
    }
}

// ---------------- node head ----------------
__global__ void node_head_k(const float* __restrict__ h1, const float* __restrict__ npW,
                            const float* __restrict__ npb, const float* __restrict__ g,
                            const float* __restrict__ beta, float* __restrict__ node_pred,
                            float* __restrict__ cls) {
    int warp = (blockIdx.x * blockDim.x + threadIdx.x) >> 5;
    int lane = threadIdx.x & 31;
    if (warp >= NN) return;
    const float* row = h1 + (size_t)warp * D_HID;
    float p[5] = {};
    for (int k = lane; k < D_HID; k += 32) {
        float hv = row[k];
        #pragma unroll
        for (int j = 0; j < 5; j++) p[j] += hv * npW[k * 5 + j];
    }
    #pragma unroll
    for (int off = 16; off; off >>= 1)
        #pragma unroll
        for (int j = 0; j < 5; j++) p[j] += __shfl_xor_sync(0xffffffffu, p[j], off);
    #pragma unroll
    for (int j = 0; j < 5; j++) p[j] += npb[j];
    float mu = (p[0] + p[1] + p[2] + p[3] + p[4]) * 0.2f;
    float var = 0.f;
    #pragma unroll
    for (int j = 0; j < 5; j++) { float t = p[j] - mu; var += t * t; }
    var *= 0.2f;
    float inv = rsqrtf(var + EPS);
    float y[5];
    #pragma unroll
    for (int j = 0; j < 5; j++) y[j] = g[j] * (p[j] - mu) * inv + beta[j];
    float mx = y[0];
    #pragma unroll
    for (int j = 1; j < 5; j++) mx = fmaxf(mx, y[j]);
    float es[5], se = 0.f;
    #pragma unroll
    for (int j = 0; j < 5; j++) { es[j] = __expf(y[j] - mx); se += es[j]; }
    float rse = 1.f / se;
    if (lane == 0) {
        #pragma unroll
        for (int j = 0; j < 5; j++) {
            node_pred[(size_t)warp * 5 + j] = y[j];
            cls[(size_t)warp * 5 + j] = es[j] * rse;
        }
    }
}

// ---------------- edge head: 512 threads, 16 edges / block ----------------
__global__ __launch_bounds__(512) void edge_head_k(
        const float* __restrict__ P, const float* __restrict__ Q,
        const float* __restrict__ cls, const float* __restrict__ efeat,
        const int* __restrict__ src, const int* __restrict__ dst,
        const float* __restrict__ W1, const float* __restrict__ b1,
        const float* __restrict__ g, const float* __restrict__ beta,
        const float* __restrict__ W2, const float* __restrict__ b2,
        float* __restrict__ out) {
    __shared__ __align__(16) float ws[16][256];
    for (int i = threadIdx.x; i < 16 * 256; i += blockDim.x) {
        int r = i >> 8, c = i & 255;
        int row = (r < 11) ? (256 + r) : (523 + r - 11);
        ws[r][c] = W1[row * 256 + c];
    }
    __syncthreads();
    int e = blockIdx.x * 16 + (threadIdx.x >> 5);
    if (e >= EE) return;
    int lane = threadIdx.x & 31;
    int s = src[e], d = dst[e];
    int f0 = lane * 8;
    float y[8];
    {
        float4 pa = *(const float4*)(P + (size_t)s * 256 + f0);
        float4 pb = *(const float4*)(P + (size_t)s * 256 + f0 + 4);
        float4 qa = *(const float4*)(Q + (size_t)d * 256 + f0);
        float4 qb = *(const float4*)(Q + (size_t)d * 256 + f0 + 4);
        float4 ba = *(const float4*)(b1 + f0);
        float4 bb = *(const float4*)(b1 + f0 + 4);
        y[0] = pa.x + qa.x + ba.x; y[1] = pa.y + qa.y + ba.y;
        y[2] = pa.z + qa.z + ba.z; y[3] = pa.w + qa.w + ba.w;
        y[4] = pb.x + qb.x + bb.x; y[5] = pb.y + qb.y + bb.y;
        y[6] = pb.z + qb.z + bb.z; y[7] = pb.w + qb.w + bb.w;
    }
    float c16[16];
    #pragma unroll
    for (int i = 0; i < 5; i++) c16[i] = cls[(size_t)s * 5 + i];
    #pragma unroll
    for (int i = 0; i < 6; i++) c16[5 + i] = efeat[(size_t)e * 6 + i];
    #pragma unroll
    for (int i = 0; i < 5; i++) c16[11 + i] = cls[(size_t)d * 5 + i];
    #pragma unroll
    for (int i = 0; i < 16; i++) {
        float4 wa = *(const float4*)&ws[i][f0];
        float4 wb = *(const float4*)&ws[i][f0 + 4];
        float ci = c16[i];
        y[0] += ci * wa.x; y[1] += ci * wa.y; y[2] += ci * wa.z; y[3] += ci * wa.w;
        y[4] += ci * wb.x; y[5] += ci * wb.y; y[6] += ci * wb.z; y[7] += ci * wb.w;
    }
    float sum = 0.f;
    #pragma unroll
    for (int i = 0; i < 8; i++) sum += y[i];
    #pragma unroll
    for (int off = 16; off; off >>= 1) sum += __shfl_xor_sync(0xffffffffu, sum, off);
    float mu = sum * (1.f / 256.f);
    float vs = 0.f;
    #pragma unroll
    for (int i = 0; i < 8; i++) { float t = y[i] - mu; vs += t * t; }
    #pragma unroll
    for (int off = 16; off; off >>= 1) vs += __shfl_xor_sync(0xffffffffu, vs, off);
    float inv = rsqrtf(vs * (1.f / 256.f) + EPS);
    float o0 = 0.f, o1 = 0.f;
    #pragma unroll
    for (int i = 0; i < 8; i++) {
        int f = f0 + i;
        float yn = g[f] * (y[i] - mu) * inv + beta[f];
        yn = fmaxf(yn, 0.f);
        o0 += yn * W2[f * 2 + 0];
        o1 += yn * W2[f * 2 + 1];
    }
    #pragma unroll
    for (int off = 16; off; off >>= 1) {
        o0 += __shfl_xor_sync(0xffffffffu, o0, off);
        o1 += __shfl_xor_sync(0xffffffffu, o1, off);
    }
    if (lane == 0) {
        out[(size_t)e * 2 + 0] = o0 + b2[0];
        out[(size_t)e * 2 + 1] = o1 + b2[1];
    }
}

// ---------------- launch ----------------
extern "C" void kernel_launch(void* const* d_in, const int* in_sizes, int n_in,
                              void* d_out, int out_size) {
    const float* h        = (const float*)d_in[0];
    const float* efeat    = (const float*)d_in[1];
    const int*   src      = (const int*)  d_in[2];
    const int*   dst      = (const int*)  d_in[3];
    const float* encWpool = (const float*)d_in[4];
    const float* encbpool = (const float*)d_in[5];
    const float* encWself = (const float*)d_in[6];
    const float* encbself = (const float*)d_in[7];
    const float* encWneigh= (const float*)d_in[8];
    const float* npW      = (const float*)d_in[9];
    const float* npb      = (const float*)d_in[10];
    const float* npg      = (const float*)d_in[11];
    const float* npbeta   = (const float*)d_in[12];
    const float* epW1     = (const float*)d_in[13];
    const float* epb1     = (const float*)d_in[14];
    const float* epg      = (const float*)d_in[15];
    const float* epbeta   = (const float*)d_in[16];
    const float* epW2     = (const float*)d_in[17];
    const float* epb2     = (const float*)d_in[18];
    const float* decWpool = (const float*)d_in[19];
    const float* decbpool = (const float*)d_in[20];
    const float* decWself = (const float*)d_in[21];
    const float* decbself = (const float*)d_in[22];
    const float* decWneigh= (const float*)d_in[23];

    float* out       = (float*)d_out;
    float* node_pred = out;                       // [NN,5]
    float* edge_pred = out + NN * 5;              // [EE,2]
    float* h2        = out + NN * 5 + EE * 2;     // [NN,128]

    float *m1, *agg1, *h1, *cls, *P, *Q, *m2, *agg2;
    cudaGetSymbolAddress((void**)&m1,  g_m1);
    cudaGetSymbolAddress((void**)&agg1,g_agg1);
    cudaGetSymbolAddress((void**)&h1,  g_h1);
    cudaGetSymbolAddress((void**)&cls, g_cls);
    cudaGetSymbolAddress((void**)&P,   g_P);
    cudaGetSymbolAddress((void**)&Q,   g_Q);
    cudaGetSymbolAddress((void**)&m2,  g_m2);
    cudaGetSymbolAddress((void**)&agg2,g_agg2);

    int mb128 = (NN + 127) / 128;   // 235

    // CSR build (shared by both SAGE layers)
    csr_zero_k<<<(NN + 255) / 256, 256>>>();
    csr_hist_k<<<(EE + 255) / 256, 256>>>(dst);
    csr_scan_k<<<1, 1024>>>();
    csr_fill_k<<<(EE + 255) / 256, 256>>>(src, dst);

    // encoder: m1 = relu(h @ encWpool + bpool)
    tgemm<false, true, true><<<dim3(1, mb128), 256>>>(
        h, encWpool, nullptr, nullptr, encbpool, m1, NN, D_IN, D_IN);

    gather_max_128<<<(NN * 32 + 255) / 256, 256>>>(m1, agg1);

    // h1 = relu(h@Wself + agg1@Wneigh + bself)
    tgemm<true, true, true><<<dim3(2, mb128), 256>>>(
        h, encWself, agg1, encWneigh, encbself, h1, NN, D_IN, D_HID);

    node_head_k<<<(NN * 32 + 255) / 256, 256>>>(h1, npW, npb, npg, npbeta, node_pred, cls);

    // P = h1 @ W1[0:256,:], Q = h1 @ W1[267:523,:]
    tgemm<false, false, false><<<dim3(2, mb128), 256>>>(
        h1, epW1, nullptr, nullptr, nullptr, P, NN, D_HID, D_HID);
    tgemm<false, false, false><<<dim3(2, mb128), 256>>>(
        h1, epW1 + 267 * 256, nullptr, nullptr, nullptr, Q, NN, D_HID, D_HID);

    edge_head_k<<<(EE + 15) / 16, 512>>>(P, Q, cls, efeat, src, dst,
                                         epW1, epb1, epg, epbeta, epW2, epb2, edge_pred);

    // decoder: m2 = relu(h1 @ decWpool + bpool)
    tgemm<false, true, true><<<dim3(2, mb128), 256>>>(
        h1, decWpool, nullptr, nullptr, decbpool, m2, NN, D_HID, D_HID);

    gather_max_256<<<(NN * 32 + 255) / 256, 256>>>(m2, agg2);

    // h2 = relu(h1@decWself + agg2@decWneigh + bself)
    tgemm<true, true, true><<<dim3(1, mb128), 256>>>(
        h1, decWself, agg2, decWneigh, decbself, h2, NN, D_HID, D_IN);
}